// round 6
// baseline (speedup 1.0000x reference)
#include <cuda_runtime.h>
#include <math.h>

#define NT 20

// scale tables: offsets into per-image anchor arrays {sc0, sc1, sc2}
// A = {9408, 2352, 588}, off = {0, 9408, 11760}, total 12348

__device__ unsigned long long g_best[192 * NT];  // (sc*64+b)*20+t : packed (iou<<32)|~a
__device__ float g_sums[192 * 3];                // sb, sce, sl1 per (sc,img)
__device__ int   g_np[192], g_nn[192];
__device__ unsigned char g_state[64][12348];     // state*32 + matched_t
__device__ float g_keys[64][12348];              // neg BCE keys (0 for non-neg)
__device__ float g_partial[192 * 3];
__device__ int   g_ctr;

__device__ __forceinline__ float blk_sum_f(float v, float* wred, int tid) {
#pragma unroll
    for (int o = 16; o; o >>= 1) v += __shfl_down_sync(0xffffffffu, v, o);
    if ((tid & 31) == 0) wred[tid >> 5] = v;
    __syncthreads();
    float r = 0.f;
    if (tid == 0) {
#pragma unroll
        for (int i = 0; i < 8; i++) r += wred[i];
    }
    __syncthreads();
    return r;  // tid 0 only
}

__device__ __forceinline__ int blk_sum_i(int v, int* wred, int tid) {
#pragma unroll
    for (int o = 16; o; o >>= 1) v += __shfl_down_sync(0xffffffffu, v, o);
    if ((tid & 31) == 0) wred[tid >> 5] = v;
    __syncthreads();
    int r = 0;
    if (tid == 0) {
#pragma unroll
        for (int i = 0; i < 8; i++) r += wred[i];
    }
    __syncthreads();
    return r;  // tid 0 only
}

// chunk mapping: blockIdx.x 0..5 -> (sc, c0, ncell, H, stride)
__device__ __forceinline__ void chunk_map(int chunk, int& sc, int& c0, int& ncell,
                                          int& H, float& stride, int& off) {
    if (chunk < 4)       { sc = 0; c0 = chunk * 784; ncell = 784; H = 56; stride = 8.f;  off = 0; }
    else if (chunk == 4) { sc = 1; c0 = 0;           ncell = 784; H = 28; stride = 16.f; off = 9408; }
    else                 { sc = 2; c0 = 0;           ncell = 196; H = 14; stride = 32.f; off = 11760; }
}

// ---------------- K0: init ----------------
__global__ void k0_init() {
    int tid = threadIdx.x;
    for (int i = tid; i < 192 * NT; i += 256) g_best[i] = 0xFFFFFFFFull;  // pack(iou=0, a=0)
    for (int i = tid; i < 192 * 3; i += 256) g_sums[i] = 0.f;
    for (int i = tid; i < 192; i += 256) { g_np[i] = 0; g_nn[i] = 0; }
    if (tid == 0) g_ctr = 0;
}

// ---------------- K1: IoU matching (chunked, target-culled) ----------------
__global__ __launch_bounds__(256) void k1_match(const float* __restrict__ tbx) {
    __shared__ float4 s_ctb[NT];
    __shared__ float  s_car[NT];
    __shared__ int    s_cti[NT];
    __shared__ unsigned long long s_best[NT];
    __shared__ int s_nact;

    const int tid = threadIdx.x;
    const int b = blockIdx.y;
    int sc, c0, ncell, H, off; float stride;
    chunk_map(blockIdx.x, sc, c0, ncell, H, stride, off);

    if (tid < NT) s_best[tid] = 0xFFFFFFFFull;
    if (tid < 32) {
        bool act = false; float4 tb = make_float4(0.f, 0.f, 0.f, 0.f);
        if (tid < NT) {
            tb = ((const float4*)tbx)[b * NT + tid];
            // anchor y-extent of this chunk's rows: [(r0-1)*stride, (r1+1)*stride]
            float ylo = ((float)(c0 / H) - 1.f) * stride;
            float yhi = ((float)(c0 / H + ncell / H) + 1.f) * stride;
            act = (tb.w > ylo) && (tb.y < yhi);
        }
        unsigned m = __ballot_sync(0xffffffffu, act);
        if (act) {  // order-preserving compaction -> deterministic
            int p = __popc(m & ((1u << tid) - 1));
            s_ctb[p] = tb;
            s_car[p] = (tb.z - tb.x) * (tb.w - tb.y);
            s_cti[p] = tid;
        }
        if (tid == 0) s_nact = __popc(m);
    }
    __syncthreads();
    const int nact = s_nact;

    for (int cell = c0 + tid; cell < c0 + ncell; cell += 256) {
        int x = cell % H, y = cell / H;
        float cx = ((float)x + 0.5f) * stride;
        float cy = ((float)y + 0.5f) * stride;
#pragma unroll
        for (int k = 0; k < 3; k++) {
            float hw = (k == 0) ? stride : ((k == 1) ? 1.25f * stride : 1.5f * stride);
            float ax0 = cx - hw, ay0 = cy - hw, ax1 = cx + hw, ay1 = cy + hw;
            float areaA = (ax1 - ax0) * (ay1 - ay0);
            int a = cell * 3 + k;
            float best = 0.f; int bt = 0;
            unsigned long long na = (unsigned long long)(unsigned int)(~a);
            for (int j = 0; j < nact; j++) {
                float4 tb = s_ctb[j];
                float iw = fminf(ax1, tb.z) - fmaxf(ax0, tb.x);
                float ih = fminf(ay1, tb.w) - fmaxf(ay0, tb.y);
                if (iw > 0.f && ih > 0.f) {
                    float inter = iw * ih;
                    float iou = inter / (areaA + s_car[j] - inter + 1e-9f);
                    int t = s_cti[j];
                    if (iou > best) { best = iou; bt = t; }  // first t wins ties
                    unsigned long long pk =
                        ((unsigned long long)__float_as_uint(iou) << 32) | na;
                    atomicMax(&s_best[t], pk);               // smaller a wins ties
                }
            }
            int state = (best >= 0.5f) ? 2 : ((best < 0.3f) ? 0 : 1);
            g_state[b][off + a] = (unsigned char)(state * 32 + bt);
        }
    }
    __syncthreads();
    if (tid < NT && s_best[tid] != 0xFFFFFFFFull)
        atomicMax(&g_best[(sc * 64 + b) * NT + tid], s_best[tid]);
}

// ---------------- Kf: forced matches (last-write-wins per (img,sc)) ----------
__global__ void kf_force() {
    int i = threadIdx.x;  // 0..191 = sc*64+b
    if (i < 192) {
        int sc = i >> 6, b = i & 63;
        int off = (sc == 0) ? 0 : ((sc == 1) ? 9408 : 11760);
        for (int t = 0; t < NT; t++) {
            unsigned int a = ~(unsigned int)(g_best[i * NT + t] & 0xFFFFFFFFull);
            g_state[b][off + a] = (unsigned char)(2 * 32 + t);
        }
    }
}

// ---------------- K2: per-anchor losses ----------------
__global__ __launch_bounds__(256) void k2_loss(
    const float* __restrict__ p1, const float* __restrict__ p2, const float* __restrict__ p3,
    const float* __restrict__ tbx, const int* __restrict__ tlb)
{
    __shared__ float4 s_tb4[NT];
    __shared__ int    s_tlab[NT];
    __shared__ float  s_wred[8];
    __shared__ int    s_iwred[8];

    const int tid = threadIdx.x;
    const int b = blockIdx.y;
    int sc, c0, ncell, H, off; float stride;
    chunk_map(blockIdx.x, sc, c0, ncell, H, stride, off);
    const float* pred = (sc == 0) ? p1 : ((sc == 1) ? p2 : p3);
    const int HW = H * H;

    if (tid < NT) {
        s_tb4[tid] = ((const float4*)tbx)[b * NT + tid];
        s_tlab[tid] = tlb[b * NT + tid];
    }
    __syncthreads();

    const float* pim = pred + (size_t)b * 24 * HW;
    float sb = 0.f, sce = 0.f, sl1 = 0.f;
    int np = 0, nn = 0;

    for (int cell = c0 + tid; cell < c0 + ncell; cell += 256) {
#pragma unroll
        for (int k = 0; k < 3; k++) {
            int a = cell * 3 + k;
            const float* pb = pim + k * 8 * HW + cell;
            float obj = __ldg(pb + 4 * HW);
            unsigned char v = g_state[b][off + a];
            int state = v >> 5;
            int t = v & 31;
            float yv = (state == 2) ? 1.f : 0.f;
            float bce = fmaxf(obj, 0.f) - obj * yv + __logf(1.f + __expf(-fabsf(obj)));
            float key = 0.f;
            if (state == 0) { key = bce; nn++; }
            g_keys[b][off + a] = key;
            if (state == 2) {
                np++; sb += bce;
                float c0v = __ldg(pb + 5 * HW);
                float c1v = __ldg(pb + 6 * HW);
                float c2v = __ldg(pb + 7 * HW);
                float m = fmaxf(c0v, fmaxf(c1v, c2v));
                float lse = m + __logf(__expf(c0v - m) + __expf(c1v - m) + __expf(c2v - m));
                int lab = s_tlab[t] - 1;
                float ct = (lab == 0) ? c0v : ((lab == 1) ? c1v : c2v);
                sce += lse - ct;
                // anchor closed form
                int x = cell % H, y = cell / H;
                float cx = ((float)x + 0.5f) * stride;
                float cy = ((float)y + 0.5f) * stride;
                float hw = (k == 0) ? stride : ((k == 1) ? 1.25f * stride : 1.5f * stride);
                float aw = (cx + hw) - (cx - hw);   // exact 2*hw
                float4 tb = s_tb4[t];
                float gw = tb.z - tb.x, gh = tb.w - tb.y;
                float gcx = (tb.x + tb.z) * 0.5f, gcy = (tb.y + tb.w) * 0.5f;
                float td0 = (gcx - cx) / aw;
                float td1 = (gcy - cy) / aw;
                float td2 = __logf(gw / aw);
                float td3 = __logf(gh / aw);
                float d;
                d = fabsf(__ldg(pb + 0 * HW) - td0); sl1 += (d < 1.f) ? 0.5f * d * d : d - 0.5f;
                d = fabsf(__ldg(pb + 1 * HW) - td1); sl1 += (d < 1.f) ? 0.5f * d * d : d - 0.5f;
                d = fabsf(__ldg(pb + 2 * HW) - td2); sl1 += (d < 1.f) ? 0.5f * d * d : d - 0.5f;
                d = fabsf(__ldg(pb + 3 * HW) - td3); sl1 += (d < 1.f) ? 0.5f * d * d : d - 0.5f;
            }
        }
    }
    __syncthreads();

    float sb_t  = blk_sum_f(sb,  s_wred, tid);
    float sce_t = blk_sum_f(sce, s_wred, tid);
    float sl1_t = blk_sum_f(sl1, s_wred, tid);
    int   np_t  = blk_sum_i(np,  s_iwred, tid);
    int   nn_t  = blk_sum_i(nn,  s_iwred, tid);
    if (tid == 0) {
        int idx = sc * 64 + b;
        if (sb_t  != 0.f) atomicAdd(&g_sums[idx * 3 + 0], sb_t);
        if (sce_t != 0.f) atomicAdd(&g_sums[idx * 3 + 1], sce_t);
        if (sl1_t != 0.f) atomicAdd(&g_sums[idx * 3 + 2], sl1_t);
        if (np_t) atomicAdd(&g_np[idx], np_t);
        if (nn_t) atomicAdd(&g_nn[idx], nn_t);
    }
}

// ---------------- K3: radix-select + per-image losses + finalize --------------
__global__ __launch_bounds__(256) void k3_select(float* __restrict__ out) {
    __shared__ float s_keys[9408];
    __shared__ unsigned int s_hist[256];
    __shared__ float s_wred[8];
    __shared__ int   s_iwred[8];
    __shared__ int   s_i[4];
    __shared__ unsigned int s_u[1];
    __shared__ int   s_last;

    const int tid = threadIdx.x;
    const int b = blockIdx.x;
    const int sc = blockIdx.y;
    int A, off;
    if (sc == 0)      { A = 9408; off = 0; }
    else if (sc == 1) { A = 2352; off = 9408; }
    else              { A = 588;  off = 11760; }
    const int idx = sc * 64 + b;

    for (int i = tid; i < A; i += 256) s_keys[i] = g_keys[b][off + i];
    if (tid == 0) { s_i[0] = g_np[idx]; s_i[1] = g_nn[idx]; }
    __syncthreads();

    const int num_pos = s_i[0];
    const int num_neg = s_i[1];
    int need = 3 * num_pos;
    if (need > num_neg) need = num_neg;

    float sum_sel = 0.f;
    if (need > 0) {
        if (tid == 0) { s_u[0] = 0u; s_i[2] = need; }
        __syncthreads();
#pragma unroll
        for (int pass = 0; pass < 4; pass++) {
            s_hist[tid] = 0u;
            __syncthreads();
            int shift = 24 - 8 * pass;
            unsigned int hi_mask = (pass == 0) ? 0u : (0xFFFFFFFFu << (shift + 8));
            unsigned int pfx = s_u[0];
            for (int a = tid; a < A; a += 256) {
                unsigned int key = __float_as_uint(s_keys[a]);
                if ((key & hi_mask) == pfx)
                    atomicAdd(&s_hist[(key >> shift) & 255], 1u);
            }
            __syncthreads();
            if (tid == 0) {
                unsigned int kk = (unsigned int)s_i[2];
                unsigned int cum = 0; int sel = 0;
                for (int d = 255; d >= 0; d--) {
                    unsigned int c = s_hist[d];
                    if (kk <= cum + c) { sel = d; kk -= cum; break; }
                    cum += c;
                }
                s_u[0] = pfx | ((unsigned int)sel << shift);
                s_i[2] = (int)kk;
            }
            __syncthreads();
        }
        unsigned int kth = s_u[0];
        float kth_val = __uint_as_float(kth);
        float sg = 0.f; int cg = 0;
        for (int a = tid; a < A; a += 256) {
            float v = s_keys[a];
            if (__float_as_uint(v) > kth) { sg += v; cg++; }
        }
        float sg_t = blk_sum_f(sg, s_wred, tid);
        int   cg_t = blk_sum_i(cg, s_iwred, tid);
        if (tid == 0) sum_sel = sg_t + (float)(need - cg_t) * kth_val;
    }

    if (tid == 0) {
        int denom_obj = num_pos + need; if (denom_obj < 1) denom_obj = 1;
        int denom_cls = num_pos;        if (denom_cls < 1) denom_cls = 1;
        int denom_loc = 4 * num_pos;    if (denom_loc < 1) denom_loc = 1;
        g_partial[idx * 3 + 0] = (g_sums[idx * 3 + 0] + sum_sel) / (float)denom_obj;
        g_partial[idx * 3 + 1] = g_sums[idx * 3 + 1] / (float)denom_cls;
        g_partial[idx * 3 + 2] = g_sums[idx * 3 + 2] / (float)denom_loc;
    }

    __threadfence();
    if (tid == 0) {
        int ticket = atomicAdd(&g_ctr, 1);
        s_last = (ticket == 191);
    }
    __syncthreads();
    if (s_last && tid < 32) {
        float o = 0.f, c = 0.f, l = 0.f;
        for (int i = tid; i < 192; i += 32) {
            o += g_partial[3 * i + 0];
            c += g_partial[3 * i + 1];
            l += g_partial[3 * i + 2];
        }
#pragma unroll
        for (int s = 16; s; s >>= 1) {
            o += __shfl_down_sync(0xffffffffu, o, s);
            c += __shfl_down_sync(0xffffffffu, c, s);
            l += __shfl_down_sync(0xffffffffu, l, s);
        }
        if (tid == 0) {
            o *= (1.f / 64.f);
            c *= (1.f / 64.f);
            l *= (1.f / 64.f);
            out[0] = o;
            out[1] = c;
            out[2] = l;
            out[3] = o + c + 2.f * l;
        }
    }
}

extern "C" void kernel_launch(void* const* d_in, const int* in_sizes, int n_in,
                              void* d_out, int out_size) {
    const float* p1 = (const float*)d_in[0];
    const float* p2 = (const float*)d_in[1];
    const float* p3 = (const float*)d_in[2];
    const float* tb = (const float*)d_in[6];
    const int*   tl = (const int*)d_in[7];

    k0_init<<<1, 256>>>();
    k1_match<<<dim3(6, 64), 256>>>(tb);
    kf_force<<<1, 192>>>();
    k2_loss<<<dim3(6, 64), 256>>>(p1, p2, p3, tb, tl);
    k3_select<<<dim3(64, 3), 256>>>((float*)d_out);
}